// round 7
// baseline (speedup 1.0000x reference)
#include <cuda_runtime.h>
#include <cuda_fp16.h>
#include <cstdint>
#include <cstddef>

// ---------------------------------------------------------------------------
// Fused GPTQ 4-bit dequant + fp16 GEMM via mma.sync (HMMA), sm_103 base arch
// (toolchain compiles at compute_103: tcgen05 unavailable).
//
// R7 change vs R6: warp tile 64x32 -> 64x64 (operand reuse: 192 -> 125 B/MMA,
// cutting L1 wavefront traffic ~27%), while KEEPING 2 CTAs/SM by shrinking
// CTAs to 128 threads (4 warps, 2m x 2n). CTA tile stays 128x128x64,
// double-buffered (64 KB smem/CTA -> 128 KB/SM).
//
//   x      : float32 [4096, 4096]
//   qweight: int32   [512, 11008]  nibble j (shift 4*j) -> k = kp*8 + j
//   qzeros : int32   [1, 1376]     nibble (n%8) -> zero for col n; +1 (GPTQ)
//   scales : float32 [1, 11008]
//   out    : float32 [4096, 11008]
//
// Pre-pass: X f32 -> f16 into g_Xh, K-permuted within each 8-group
// (pairs (t, t+4)) to match the cheap nibble extraction
// ((q >> 4t) & 0x000F000F) | 0x64006400. Same permutation on A and B
// => contraction unchanged.
// ---------------------------------------------------------------------------

static constexpr int M_DIM = 4096;
static constexpr int K_DIM = 4096;
static constexpr int N_DIM = 11008;

static constexpr int BM = 128;
static constexpr int BN = 128;
static constexpr int BK = 64;                    // halves (128 B)
static constexpr int CHUNKS = K_DIM / BK;        // 64
static constexpr int NTHREADS = 128;             // 4 warps

// dynamic smem: A 2x16KB, B 2x16KB = 64 KB (2 CTAs/SM -> 128 KB/SM)
static constexpr uint32_t A_SZ = BM * 128;       // 16384 B per stage
static constexpr uint32_t B_SZ = BN * 128;       // 16384 B per stage
static constexpr uint32_t SMEM_BYTES = 2 * A_SZ + 2 * B_SZ;  // 65536

__device__ __half g_Xh[(size_t)M_DIM * K_DIM];   // 32 MB scratch (static)

// ---------------- helpers ----------------
__device__ __forceinline__ uint32_t h2u(__half2 h) { return *reinterpret_cast<uint32_t*>(&h); }
__device__ __forceinline__ __half2  u2h(uint32_t u) { return *reinterpret_cast<__half2*>(&u); }
__device__ __forceinline__ float    rnd16(float x) { return __half2float(__float2half_rn(x)); }

__device__ __forceinline__ void cp16(uint32_t dst, const void* src) {
    asm volatile("cp.async.cg.shared.global [%0], [%1], 16;" :: "r"(dst), "l"(src));
}
__device__ __forceinline__ void ldsm4(uint32_t* r, uint32_t addr) {
    asm volatile("ldmatrix.sync.aligned.m8n8.x4.shared.b16 {%0,%1,%2,%3}, [%4];"
                 : "=r"(r[0]), "=r"(r[1]), "=r"(r[2]), "=r"(r[3]) : "r"(addr));
}
__device__ __forceinline__ void mma16816(float* c, const uint32_t* a,
                                         uint32_t b0, uint32_t b1) {
    asm volatile("mma.sync.aligned.m16n8k16.row.col.f32.f16.f16.f32 "
                 "{%0,%1,%2,%3}, {%4,%5,%6,%7}, {%8,%9}, {%0,%1,%2,%3};"
                 : "+f"(c[0]), "+f"(c[1]), "+f"(c[2]), "+f"(c[3])
                 : "r"(a[0]), "r"(a[1]), "r"(a[2]), "r"(a[3]), "r"(b0), "r"(b1));
}

// ---------------------------------------------------------------------------
// Pre-pass: f32 -> f16 with per-8-group K permutation (pairs (t, t+4)).
// ---------------------------------------------------------------------------
__global__ void __launch_bounds__(256)
convert_x(const float* __restrict__ X) {
    const size_t e = (size_t)blockIdx.x * blockDim.x + threadIdx.x;
    if (e >= (size_t)M_DIM * (K_DIM / 8)) return;
    const float4* s = reinterpret_cast<const float4*>(X) + e * 2;
    const float4 lo = s[0];
    const float4 hi = s[1];
    uint4 o;
    o.x = h2u(__floats2half2_rn(lo.x, hi.x));
    o.y = h2u(__floats2half2_rn(lo.y, hi.y));
    o.z = h2u(__floats2half2_rn(lo.z, hi.z));
    o.w = h2u(__floats2half2_rn(lo.w, hi.w));
    reinterpret_cast<uint4*>(g_Xh)[e] = o;
}

// ---------------------------------------------------------------------------
__global__ void __launch_bounds__(NTHREADS, 2)
gemm_mma(const int*   __restrict__ qweight,
         const int*   __restrict__ qzeros,
         const float* __restrict__ scales,
         float*       __restrict__ Y) {
    extern __shared__ char smem[];
    const uint32_t sb = (uint32_t)__cvta_generic_to_shared(smem);
    const uint32_t aOff[2] = {0u, A_SZ};
    const uint32_t bOff[2] = {2 * A_SZ, 2 * A_SZ + B_SZ};

    const int tid  = threadIdx.x;
    const int warp = tid >> 5;
    const int lane = tid & 31;
    const int wm   = warp >> 1;      // 0..1  (64-row slice)
    const int wn   = warp & 1;       // 0..1  (64-col slice)
    const int bm   = blockIdx.y * BM;
    const int bn   = blockIdx.x * BN;

    // dequant mapping: one column per thread, 8 packed rows each
    const int gcol = bn + tid;
    const int zraw = (qzeros[gcol >> 3] >> ((gcol & 7) * 4)) & 0xF;
    const __half2 s2v = __half2half2(__float2half_rn(scales[gcol]));
    const __half2 z2  = __half2half2(__float2half_rn((float)(1025 + zraw)));
    const int* qcol = qweight + gcol;

    float acc[4][8][4];
#pragma unroll
    for (int i = 0; i < 4; ++i)
#pragma unroll
        for (int j = 0; j < 8; ++j)
#pragma unroll
            for (int t = 0; t < 4; ++t) acc[i][j][t] = 0.0f;

    // ---- prologue: A chunk 0 + q chunk 0 ----
#pragma unroll
    for (int i = 0; i < 8; ++i) {
        const int e = tid + i * NTHREADS;
        const int r = e >> 3, g = e & 7;
        const uint32_t dst = sb + aOff[0] +
            (uint32_t)(r * 128 + ((g * 16) ^ ((r & 7) << 4)));
        cp16(dst, g_Xh + (size_t)(bm + r) * K_DIM + g * 8);
    }
    asm volatile("cp.async.commit_group;" ::: "memory");
    uint32_t q[8];
#pragma unroll
    for (int pr = 0; pr < 8; ++pr)
        q[pr] = (uint32_t)qcol[(size_t)pr * N_DIM];

    for (int c = 0; c < CHUNKS; ++c) {
        const int buf = c & 1;

        // ---- dequant B(c) -> STS (8 packed rows per thread) ----
        {
            const uint32_t bB   = sb + bOff[buf];
            const uint32_t brow = (uint32_t)tid * 128;
            const uint32_t bx   = (uint32_t)(tid & 7) << 4;
#pragma unroll
            for (int pr = 0; pr < 8; ++pr) {
                const uint32_t w = q[pr];
                uint32_t u[4];
#pragma unroll
                for (int t = 0; t < 4; ++t) {
                    const uint32_t hb = ((w >> (4 * t)) & 0x000F000Fu) | 0x64006400u;
                    u[t] = h2u(__hmul2(__hsub2(u2h(hb), z2), s2v));
                }
                const uint32_t dst = bB + brow + (((uint32_t)pr * 16) ^ bx);
                asm volatile("st.shared.v4.b32 [%0], {%1,%2,%3,%4};"
                             :: "r"(dst), "r"(u[0]), "r"(u[1]), "r"(u[2]), "r"(u[3])
                             : "memory");
            }
        }

        // ---- prefetch chunk c+1 (A via cp.async, q via LDG) ----
        if (c + 1 < CHUNKS) {
            const uint32_t aB = sb + aOff[buf ^ 1];
            const int k0 = (c + 1) * BK;
#pragma unroll
            for (int i = 0; i < 8; ++i) {
                const int e = tid + i * NTHREADS;
                const int r = e >> 3, g = e & 7;
                const uint32_t dst = aB +
                    (uint32_t)(r * 128 + ((g * 16) ^ ((r & 7) << 4)));
                cp16(dst, g_Xh + (size_t)(bm + r) * K_DIM + k0 + g * 8);
            }
            asm volatile("cp.async.commit_group;" ::: "memory");
#pragma unroll
            for (int pr = 0; pr < 8; ++pr)
                q[pr] = (uint32_t)qcol[(size_t)((c + 1) * 8 + pr) * N_DIM];
            asm volatile("cp.async.wait_group 1;" ::: "memory");
        } else {
            asm volatile("cp.async.wait_group 0;" ::: "memory");
        }
        __syncthreads();   // A(c) + B(c) visible

        // ---- MMA over stage buf: warp tile 64(m) x 64(n) ----
        const uint32_t aB = sb + aOff[buf];
        const uint32_t bB = sb + bOff[buf];
#pragma unroll
        for (int kk = 0; kk < 4; ++kk) {
            const uint32_t kb = kk * 32;
            uint32_t a[4][4], b[4][4];
#pragma unroll
            for (int j = 0; j < 4; ++j) {
                const int row = wn * 64 + j * 16 + ((lane >> 4) << 3) + (lane & 7);
                const uint32_t addr = bB + row * 128 +
                    ((kb + (((lane >> 3) & 1) << 4)) ^ ((row & 7) << 4));
                ldsm4(b[j], addr);
            }
#pragma unroll
            for (int i = 0; i < 4; ++i) {
                const int row = wm * 64 + i * 16 + (lane & 15);
                const uint32_t addr = aB + row * 128 +
                    ((kb + ((lane >> 4) << 4)) ^ ((row & 7) << 4));
                ldsm4(a[i], addr);
            }
#pragma unroll
            for (int i = 0; i < 4; ++i)
#pragma unroll
                for (int j = 0; j < 4; ++j) {
                    mma16816(acc[i][2 * j],     a[i], b[j][0], b[j][1]);
                    mma16816(acc[i][2 * j + 1], a[i], b[j][2], b[j][3]);
                }
        }
        __syncthreads();   // all reads of stage buf done before reuse
    }

    // ---- epilogue: round via fp16, store f32 ----
#pragma unroll
    for (int i = 0; i < 4; ++i) {
        const int m0 = bm + wm * 64 + i * 16 + (lane >> 2);
        float* y0 = Y + (size_t)m0 * N_DIM;
        float* y1 = y0 + (size_t)8 * N_DIM;
#pragma unroll
        for (int jj = 0; jj < 8; ++jj) {
            const int n0 = bn + wn * 64 + jj * 8 + 2 * (lane & 3);
            float2 v0, v1;
            v0.x = rnd16(acc[i][jj][0]);
            v0.y = rnd16(acc[i][jj][1]);
            v1.x = rnd16(acc[i][jj][2]);
            v1.y = rnd16(acc[i][jj][3]);
            *reinterpret_cast<float2*>(y0 + n0) = v0;
            *reinterpret_cast<float2*>(y1 + n0) = v1;
        }
    }
}

// ---------------------------------------------------------------------------
extern "C" void kernel_launch(void* const* d_in, const int* in_sizes, int n_in,
                              void* d_out, int out_size) {
    const float* x       = (const float*)d_in[0];
    const int*   qweight = (const int*)d_in[1];
    const int*   qzeros  = (const int*)d_in[2];
    const float* scales  = (const float*)d_in[3];
    float*       out     = (float*)d_out;

    cudaFuncSetAttribute(gemm_mma,
                         cudaFuncAttributeMaxDynamicSharedMemorySize, SMEM_BYTES);

    const int groups = M_DIM * (K_DIM / 8);
    convert_x<<<(groups + 255) / 256, 256>>>(x);

    dim3 grid(N_DIM / BN, M_DIM / BM);   // 86 x 32
    gemm_mma<<<grid, NTHREADS, SMEM_BYTES>>>(qweight, qzeros, scales, out);
}